// round 1
// baseline (speedup 1.0000x reference)
#include <cuda_runtime.h>
#include <cuda_bf16.h>

// CostVolumeConcat: out (B, 2C, D, H, W) fp32
//   out[b, c,      d, h, w] = (w >= d) ? left [b, c, h, w]     : 0
//   out[b, C + c,  d, h, w] = (w >= d) ? right[b, c, h, w - d] : 0
// B=4, C=32, D=48, H=64, W=128.
// Pure store-bound: 402.7 MB written, 8 MB read. One CTA per (b,c,h) row,
// rows cached in smem, all 96 output rows (48 d-levels x 2 sides) emitted
// as coalesced float4 stores.

#define W_ 128
#define H_ 64
#define C_ 32
#define D_ 48
#define B_ 4

__global__ __launch_bounds__(256) void cost_volume_concat_kernel(
    const float* __restrict__ left,
    const float* __restrict__ right,
    float* __restrict__ out)
{
    __shared__ float sL[W_];
    __shared__ float sR[W_];

    const int h = blockIdx.x;
    const int c = blockIdx.y;
    const int b = blockIdx.z;
    const int t = threadIdx.x;

    // Load this (b,c,h) row of left and right into smem (float4, coalesced).
    const size_t in_off = ((size_t)((b * C_ + c) * H_ + h)) * W_;
    if (t < 32) {
        ((float4*)sL)[t] = ((const float4*)(left + in_off))[t];
    } else if (t < 64) {
        ((float4*)sR)[t - 32] = ((const float4*)(right + in_off))[t - 32];
    }
    __syncthreads();

    // Output bases for this row. Channel layout: [0..C) = cost_l, [C..2C) = cost_r.
    float* const outL = out + (((size_t)(b * 2 * C_ + c) * D_) * H_ + h) * W_;
    float* const outR = out + (((size_t)(b * 2 * C_ + C_ + c) * D_) * H_ + h) * W_;
    const size_t dstride = (size_t)H_ * W_;   // elements between d-levels

    // 48 d-levels x 32 float4 per row = 1536 float4 items per side; 6 passes of 256.
    // i>>5 = d (warp-uniform), i&31 = w4 (lane) -> coalesced STG.128.

    // ---- left side: broadcast row with leading-zero mask ----
    #pragma unroll
    for (int it = 0; it < 6; it++) {
        const int i  = t + it * 256;
        const int d  = i >> 5;
        const int w4 = i & 31;
        const int w0 = w4 << 2;
        float4 v = ((const float4*)sL)[w4];
        if (w0 < d) {  // only boundary warps touch this
            v.x = (w0     >= d) ? v.x : 0.0f;
            v.y = (w0 + 1 >= d) ? v.y : 0.0f;
            v.z = (w0 + 2 >= d) ? v.z : 0.0f;
            v.w = (w0 + 3 >= d) ? v.w : 0.0f;
        }
        ((float4*)(outL + (size_t)d * dstride))[w4] = v;
    }

    // ---- right side: shifted row (w - d) with leading-zero mask ----
    #pragma unroll
    for (int it = 0; it < 6; it++) {
        const int i  = t + it * 256;
        const int d  = i >> 5;
        const int w4 = i & 31;
        const int s  = (w4 << 2) - d;      // source index of first lane element
        // Clamp (mirrors the reference's clip) so smem reads stay in-bounds,
        // then mask to zero where w < d.
        const int s0 = s     < 0 ? 0 : s;
        const int s1 = s + 1 < 0 ? 0 : s + 1;
        const int s2 = s + 2 < 0 ? 0 : s + 2;
        const int s3 = s + 3 < 0 ? 0 : s + 3;
        float4 v;
        v.x = (s     >= 0) ? sR[s0] : 0.0f;
        v.y = (s + 1 >= 0) ? sR[s1] : 0.0f;
        v.z = (s + 2 >= 0) ? sR[s2] : 0.0f;
        v.w = (s + 3 >= 0) ? sR[s3] : 0.0f;
        ((float4*)(outR + (size_t)d * dstride))[w4] = v;
    }
}

extern "C" void kernel_launch(void* const* d_in, const int* in_sizes, int n_in,
                              void* d_out, int out_size)
{
    const float* left  = (const float*)d_in[0];
    const float* right = (const float*)d_in[1];
    float* out = (float*)d_out;

    dim3 grid(H_, C_, B_);   // (64, 32, 4) = 8192 CTAs
    cost_volume_concat_kernel<<<grid, 256>>>(left, right, out);
}

// round 3
// speedup vs baseline: 1.0982x; 1.0982x over previous
#include <cuda_runtime.h>
#include <cuda_bf16.h>

// CostVolumeConcat: out (B, 2C, D, H, W) fp32
//   out[b, c,     d, h, w] = (w >= d) ? left [b, c, h, w]     : 0
//   out[b, C + c, d, h, w] = (w >= d) ? right[b, c, h, w - d] : 0
// B=4, C=32, D=48, H=64, W=128.
// Store-bound (403 MB out, 8 MB in). One CTA per (b,c,h) row.
// R2: all smem reads are conflict-free LDS.128; right-side shift done with
// two aligned float4 loads + warp-uniform register permute (dr = warp&3 is
// loop-invariant). Streaming stores via st.global.cs.

#define W_ 128
#define H_ 64
#define C_ 32
#define D_ 48
#define B_ 4
#define DSTR4 ((H_ * W_) / 4)   // float4 stride between d-levels = 2048

__global__ __launch_bounds__(256) void cost_volume_concat_kernel(
    const float* __restrict__ left,
    const float* __restrict__ right,
    float* __restrict__ out)
{
    __shared__ float4 sL[W_ / 4];
    __shared__ float4 sR[W_ / 4];

    const int h = blockIdx.x;
    const int c = blockIdx.y;
    const int b = blockIdx.z;
    const int t = threadIdx.x;

    const size_t in_off = ((size_t)((b * C_ + c) * H_ + h)) * W_;
    if (t < 32) {
        sL[t] = ((const float4*)(left + in_off))[t];
    } else if (t < 64) {
        sR[t - 32] = ((const float4*)(right + in_off))[t - 32];
    }
    __syncthreads();

    const int warp = t >> 5;
    const int w4   = t & 31;
    const int w0   = w4 << 2;

    // Output bases (float4 units). Channels: [0..C) = cost_l, [C..2C) = cost_r.
    float4* pL = (float4*)out + ((((size_t)(b * 2 * C_ + c)       * D_ + warp) * H_ + h) * W_) / 4 + w4;
    float4* pR = (float4*)out + ((((size_t)(b * 2 * C_ + C_ + c)  * D_ + warp) * H_ + h) * W_) / 4 + w4;

    // ---- left: row value is loop-invariant (one LDS.128 total) ----
    const float4 vbase = sL[w4];
    #pragma unroll
    for (int it = 0; it < 6; it++) {
        const int d = warp + 8 * it;
        float4 v = vbase;
        if (w0 < d) {                       // boundary warps only
            v.x = (w0     >= d) ? v.x : 0.0f;
            v.y = (w0 + 1 >= d) ? v.y : 0.0f;
            v.z = (w0 + 2 >= d) ? v.z : 0.0f;
            v.w = (w0 + 3 >= d) ? v.w : 0.0f;
        }
        __stcs((float4*)pL, v);
        pL += 8 * DSTR4;
    }

    // ---- right: shifted row. d = warp + 8*it, dr = d&3 = warp&3 (invariant),
    //      dq = d>>2 = (warp>>2) + 2*it. Element j of lane w4 reads
    //      sR_flat[4*w4 - d + j]; OOB float4 -> zero reproduces the w<d mask.
    const int dr = warp & 3;
    int ib = w4 - (warp >> 2);              // block index at it=0; -2 per iter
    const float4 z4 = make_float4(0.f, 0.f, 0.f, 0.f);

    if (dr == 0) {
        #pragma unroll
        for (int it = 0; it < 6; it++) {
            float4 v = (ib >= 0) ? sR[ib] : z4;
            __stcs((float4*)pR, v);
            pR += 8 * DSTR4;  ib -= 2;
        }
    } else if (dr == 1) {
        #pragma unroll
        for (int it = 0; it < 6; it++) {
            float4 Bv = (ib     >= 0) ? sR[ib]     : z4;
            float4 Av = (ib - 1 >= 0) ? sR[ib - 1] : z4;
            float4 v = make_float4(Av.w, Bv.x, Bv.y, Bv.z);
            __stcs((float4*)pR, v);
            pR += 8 * DSTR4;  ib -= 2;
        }
    } else if (dr == 2) {
        #pragma unroll
        for (int it = 0; it < 6; it++) {
            float4 Bv = (ib     >= 0) ? sR[ib]     : z4;
            float4 Av = (ib - 1 >= 0) ? sR[ib - 1] : z4;
            float4 v = make_float4(Av.z, Av.w, Bv.x, Bv.y);
            __stcs((float4*)pR, v);
            pR += 8 * DSTR4;  ib -= 2;
        }
    } else {
        #pragma unroll
        for (int it = 0; it < 6; it++) {
            float4 Bv = (ib     >= 0) ? sR[ib]     : z4;
            float4 Av = (ib - 1 >= 0) ? sR[ib - 1] : z4;
            float4 v = make_float4(Av.y, Av.z, Av.w, Bv.x);
            __stcs((float4*)pR, v);
            pR += 8 * DSTR4;  ib -= 2;
        }
    }
}

extern "C" void kernel_launch(void* const* d_in, const int* in_sizes, int n_in,
                              void* d_out, int out_size)
{
    const float* left  = (const float*)d_in[0];
    const float* right = (const float*)d_in[1];
    float* out = (float*)d_out;

    dim3 grid(H_, C_, B_);   // (64, 32, 4) = 8192 CTAs
    cost_volume_concat_kernel<<<grid, 256>>>(left, right, out);
}